// round 5
// baseline (speedup 1.0000x reference)
#include <cuda_runtime.h>
#include <cuda_bf16.h>
#include <math.h>

// inputs (metadata order): x[f32] (unused), src[i32 E], dst[i32 E],
// path_len[i32 E], b[f32 5]. output: f32 N_NODES*N_NODES.
//
// out = zeros; out[src[i], dst[i]] = b[min(path_len[i],5)-1], LAST dup wins.
//
// No memset: keys live in NaN-payload space (KEY_BASE = 0x7F800001). As signed
// ints every key exceeds any finite float bit pattern and the 0xAA poison
// (negative), so atomicMax needs no clean baseline.
//
//   Pass 0: g_vals[i] = b[min(plen[i],5)-1]          (16 MB scratch)
//   Pass A: red.max(out_i[src*n+dst], KEY_BASE + i)  (last i wins)
//   Pass B: full int4 sweep; key -> g_vals[key-BASE]; all-zero groups skipped
//           (zero cell == untouched this replay == correct value 0).

#ifndef MAX_PATH_DISTANCE
#define MAX_PATH_DISTANCE 5
#endif

#define KEY_BASE 0x7F800001
#define E_MAX (4 * 1024 * 1024)

__device__ float g_vals[E_MAX];

// ---------------- Pass 0: per-pair value precompute ----------------
__global__ void vals_kernel(const int* __restrict__ plen,
                            const float* __restrict__ b,
                            int n_pairs) {
    int t = blockIdx.x * blockDim.x + threadIdx.x;
    int base = t * 4;
    if (base >= n_pairs) return;
    if (base + 3 < n_pairs) {
        int4 p = *reinterpret_cast<const int4*>(plen + base);
        float4 r;
        r.x = __ldg(&b[min(p.x, MAX_PATH_DISTANCE) - 1]);
        r.y = __ldg(&b[min(p.y, MAX_PATH_DISTANCE) - 1]);
        r.z = __ldg(&b[min(p.z, MAX_PATH_DISTANCE) - 1]);
        r.w = __ldg(&b[min(p.w, MAX_PATH_DISTANCE) - 1]);
        *reinterpret_cast<float4*>(g_vals + base) = r;
    } else {
        for (int k = base; k < n_pairs; ++k)
            g_vals[k] = __ldg(&b[min(plen[k], MAX_PATH_DISTANCE) - 1]);
    }
}

// ---------------- Pass A: deterministic scatter ----------------
__device__ __forceinline__ void red_max(int* p, int v) {
    asm volatile("red.global.max.s32 [%0], %1;" :: "l"(p), "r"(v) : "memory");
}

__global__ void scatter_max_kernel(const int* __restrict__ src,
                                   const int* __restrict__ dst,
                                   int* __restrict__ out_i,
                                   int n_pairs, int n_nodes) {
    int t = blockIdx.x * blockDim.x + threadIdx.x;
    int base = t * 8;
    if (base >= n_pairs) return;

    if (base + 7 < n_pairs) {
        int4 s0 = *reinterpret_cast<const int4*>(src + base);
        int4 s1 = *reinterpret_cast<const int4*>(src + base + 4);
        int4 d0 = *reinterpret_cast<const int4*>(dst + base);
        int4 d1 = *reinterpret_cast<const int4*>(dst + base + 4);

        long long p0 = (long long)s0.x * n_nodes + d0.x;
        long long p1 = (long long)s0.y * n_nodes + d0.y;
        long long p2 = (long long)s0.z * n_nodes + d0.z;
        long long p3 = (long long)s0.w * n_nodes + d0.w;
        long long p4 = (long long)s1.x * n_nodes + d1.x;
        long long p5 = (long long)s1.y * n_nodes + d1.y;
        long long p6 = (long long)s1.z * n_nodes + d1.z;
        long long p7 = (long long)s1.w * n_nodes + d1.w;

        red_max(out_i + p0, KEY_BASE + base + 0);
        red_max(out_i + p1, KEY_BASE + base + 1);
        red_max(out_i + p2, KEY_BASE + base + 2);
        red_max(out_i + p3, KEY_BASE + base + 3);
        red_max(out_i + p4, KEY_BASE + base + 4);
        red_max(out_i + p5, KEY_BASE + base + 5);
        red_max(out_i + p6, KEY_BASE + base + 6);
        red_max(out_i + p7, KEY_BASE + base + 7);
    } else {
        for (int k = base; k < n_pairs; ++k) {
            long long pos = (long long)src[k] * n_nodes + dst[k];
            red_max(out_i + pos, KEY_BASE + k);
        }
    }
}

// ---------------- Pass B: decode sweep ----------------
__device__ __forceinline__ void decode_group(int* __restrict__ out_i, int g) {
    int4 v = *reinterpret_cast<const int4*>(out_i + g * 4);
    if ((v.x | v.y | v.z | v.w) == 0) return;   // untouched -> already correct 0
    float4 r;
    r.x = (v.x >= KEY_BASE) ? __ldg(&g_vals[v.x - KEY_BASE]) : 0.0f;
    r.y = (v.y >= KEY_BASE) ? __ldg(&g_vals[v.y - KEY_BASE]) : 0.0f;
    r.z = (v.z >= KEY_BASE) ? __ldg(&g_vals[v.z - KEY_BASE]) : 0.0f;
    r.w = (v.w >= KEY_BASE) ? __ldg(&g_vals[v.w - KEY_BASE]) : 0.0f;
    *reinterpret_cast<float4*>(out_i + g * 4) = r;
}

__global__ void decode_kernel(int* __restrict__ out_i, int total4) {
    int half = total4 >> 1;
    int t = blockIdx.x * blockDim.x + threadIdx.x;
    if (t < half) {
        // two independent int4 groups a half-matrix apart -> 2x load MLP
        decode_group(out_i, t);
        decode_group(out_i, t + half);
    } else if (half * 2 + (t - half) < total4) {
        decode_group(out_i, half * 2 + (t - half));   // odd tail (unused: 16M even)
    }
}

extern "C" void kernel_launch(void* const* d_in, const int* in_sizes, int n_in,
                              void* d_out, int out_size) {
    const int* src  = (const int*)d_in[1];
    const int* dst  = (const int*)d_in[2];
    const int* plen = (const int*)d_in[3];
    const float* b  = (const float*)d_in[4];

    int n_pairs = in_sizes[1];
    int n_nodes = (int)llround(sqrt((double)out_size));
    int* out_i = (int*)d_out;

    // Pass 0: per-pair values into scratch
    {
        int threads = 256;
        int work = (n_pairs + 3) / 4;
        int blocks = (work + threads - 1) / threads;
        vals_kernel<<<blocks, threads>>>(plen, b, n_pairs);
    }

    // Pass A: last-write-wins scatter (fire-and-forget REDG)
    {
        int threads = 256;
        int work = (n_pairs + 7) / 8;
        int blocks = (work + threads - 1) / threads;
        scatter_max_kernel<<<blocks, threads>>>(src, dst, out_i,
                                                n_pairs, n_nodes);
    }

    // Pass B: decode sweep
    {
        int total4 = out_size / 4;
        int half = total4 >> 1;
        int threads = 256;
        int blocks = (half + threads - 1) / threads;
        decode_kernel<<<blocks, threads>>>(out_i, total4);
    }
}